// round 7
// baseline (speedup 1.0000x reference)
#include <cuda_runtime.h>
#include <cstdint>

#define N_NODES 12288
#define H_DIM   128
#define E_EDGES 393216
#define NEGVAL  (-1000000000.0f)
#define ROW4    (N_NODES / 4)      // 3072 float4 per row
#define CAP     256                // bucket capacity per row (Poisson(32), max~65)

// Static scratch (no cudaMalloc allowed). g_cursor is zero-init at module
// load and self-restored to zero by fill_merge_kernel every launch.
__device__ float g_d1[N_NODES];
__device__ float g_d2[N_NODES];
__device__ int   g_cursor[N_NODES];
__device__ int2  g_bucket[(size_t)N_NODES * CAP];   // (src_col, float_bits(weight))

// ---------------------------------------------------------------------------
// A: per-node dots (1 warp/node; grid has exactly N warps) + edge placement
//    (1 thread/edge). Placement stores only (src, weight) -> independent of
//    the dots, so both live in one kernel.
// ---------------------------------------------------------------------------
__global__ void dots_place_kernel(const float* __restrict__ h,
                                  const float* __restrict__ W,
                                  const int*   __restrict__ src,
                                  const int*   __restrict__ dst,
                                  const float* __restrict__ wts) {
    int t    = (int)(blockIdx.x * blockDim.x + threadIdx.x);
    int gw   = t >> 5;
    int lane = t & 31;

    // edge placement: independent loads first
    int   s  = src[t];
    int   d  = dst[t];
    float w  = wts[t];

    // dots: warp gw handles node gw (E/32 == N exactly)
    {
        const float4* hr4 = (const float4*)(h + (size_t)gw * H_DIM);
        const float4* w14 = (const float4*)(W);
        const float4* w24 = (const float4*)(W + H_DIM);
        float4 hv = __ldg(&hr4[lane]);
        float4 w1 = __ldg(&w14[lane]);
        float4 w2 = __ldg(&w24[lane]);
        float s1 = fmaf(hv.x, w1.x, fmaf(hv.y, w1.y, fmaf(hv.z, w1.z, hv.w * w1.w)));
        float s2 = fmaf(hv.x, w2.x, fmaf(hv.y, w2.y, fmaf(hv.z, w2.z, hv.w * w2.w)));
#pragma unroll
        for (int off = 16; off; off >>= 1) {
            s1 += __shfl_down_sync(0xffffffffu, s1, off);
            s2 += __shfl_down_sync(0xffffffffu, s2, off);
        }
        if (lane == 0) { g_d1[gw] = s1; g_d2[gw] = s2; }
    }

    int pos = atomicAdd(&g_cursor[d], 1);
    if (pos < CAP) {
        g_bucket[(size_t)d * CAP + pos] = make_int2(s, __float_as_int(w));
    }
}

// ---------------------------------------------------------------------------
// D: software-pipelined fill + merge + cursor reset.
//    For each row: build 48KB row in smem (NEG + edges), stream out __stcs.
//    All global loads for row r+stride are issued while row r is being
//    filled/stored, so no load latency sits between barriers.
// ---------------------------------------------------------------------------
__global__ __launch_bounds__(512) void fill_merge_kernel(
        float4* __restrict__ out,
        const float* __restrict__ W,
        const float* __restrict__ b) {
    __shared__ float row[N_NODES];               // exactly 48 KB
    __shared__ int   s_cnt_n;
    float4* row4 = (float4*)row;
    const float4 v = make_float4(NEGVAL, NEGVAL, NEGVAL, NEGVAL);

    const float wlin = __ldg(&W[2 * H_DIM]);
    const float bias = __ldg(&b[0]);
    const int   tid  = threadIdx.x;

    int r = blockIdx.x;                          // rows strided by gridDim

    // ---- prologue: metadata + entry + value for first row ----
    int   cnt = 0;
    int   col = 0;
    float val = 0.0f;
    {
        int c = g_cursor[r];                     // ALL threads read first...
        cnt = (c < CAP) ? c : CAP;
        if (tid < cnt) {
            int2 ev = g_bucket[(size_t)r * CAP + tid];
            col = ev.x;
            val = g_d1[r] + g_d2[ev.x] + fmaf(__int_as_float(ev.y), wlin, bias);
        }
        __syncthreads();                         // ...then t0 may reset
        if (tid == 0) g_cursor[r] = 0;           // self-restore for next launch
    }

    while (true) {
        const int  rn        = r + (int)gridDim.x;
        const bool have_next = (rn < N_NODES);

        // -- prefetch next row's metadata + entries (issued before fill) --
        int2  evn = make_int2(0, 0);
        float d1n = 0.0f;
        if (have_next) {
            if (tid == 0) {
                int c = g_cursor[rn];            // only t0 touches cursor here
                s_cnt_n = (c < CAP) ? c : CAP;
                g_cursor[rn] = 0;                // self-restore for next launch
            }
            d1n = g_d1[rn];
            if (tid < CAP) evn = g_bucket[(size_t)rn * CAP + tid];  // no cnt dep
        }

        // -- fill current row with NEG --
#pragma unroll
        for (int i = tid; i < ROW4; i += 512) row4[i] = v;
        __syncthreads();                         // also publishes s_cnt_n

        // -- merge current row's edges (values already in registers) --
        if (tid < cnt) row[col] = val;           // dup races benign
        __syncthreads();

        // -- stream current row out --
        float4* dstp = out + (size_t)r * ROW4;
#pragma unroll
        for (int i = tid; i < ROW4; i += 512) __stcs(&dstp[i], row4[i]);

        if (!have_next) break;

        // -- compute next row's values; bucket loads landed during store loop --
        cnt = s_cnt_n;
        col = evn.x;
        val = d1n + g_d2[evn.x] + fmaf(__int_as_float(evn.y), wlin, bias);

        r = rn;
        __syncthreads();                         // stores done before smem refill
    }
}

// ---------------------------------------------------------------------------
// Launch. Input order (metadata): h, sources, dests, weights, W, b
// ---------------------------------------------------------------------------
extern "C" void kernel_launch(void* const* d_in, const int* in_sizes, int n_in,
                              void* d_out, int out_size) {
    const float* h       = (const float*)d_in[0];
    const int*   sources = (const int*)  d_in[1];
    const int*   dests   = (const int*)  d_in[2];
    const float* weights = (const float*)d_in[3];
    const float* W       = (const float*)d_in[4];
    const float* b       = (const float*)d_in[5];
    float*       out     = (float*)d_out;

    // A: dots + edge placement. E threads; warp i == node i.
    dots_place_kernel<<<E_EDGES / 256, 256>>>(h, W, sources, dests, weights);

    // D: pipelined fill + merge. 4 blocks/SM (48KB smem each), one wave.
    fill_merge_kernel<<<148 * 4, 512>>>((float4*)out, W, b);
}

// round 8
// speedup vs baseline: 1.3412x; 1.3412x over previous
#include <cuda_runtime.h>
#include <cstdint>

#define N_NODES 12288
#define H_DIM   128
#define E_EDGES 393216
#define NEGVAL  (-1000000000.0f)
#define ROW4    (N_NODES / 4)      // 3072 float4 per row
#define CAP     256                // bucket capacity per row (Poisson(32), max~65)

// Static scratch. g_cursor zero-init at load; self-restored by D each launch.
__device__ float g_d1[N_NODES];
__device__ float g_d2[N_NODES];
__device__ int   g_cursor[N_NODES];
__device__ int2  g_bucket[(size_t)N_NODES * CAP];   // (src_col, float_bits(value))

// ---------------------------------------------------------------------------
// A1: per-node dots. 1 warp/node, 1 float4 load per lane.
// ---------------------------------------------------------------------------
__global__ void dots_kernel(const float* __restrict__ h,
                            const float* __restrict__ W) {
    int t    = (int)(blockIdx.x * blockDim.x + threadIdx.x);
    int gw   = t >> 5;
    int lane = t & 31;
    if (gw >= N_NODES) return;

    const float4* hr4 = (const float4*)(h + (size_t)gw * H_DIM);
    const float4* w14 = (const float4*)(W);
    const float4* w24 = (const float4*)(W + H_DIM);
    float4 hv = __ldg(&hr4[lane]);
    float4 w1 = __ldg(&w14[lane]);
    float4 w2 = __ldg(&w24[lane]);
    float s1 = fmaf(hv.x, w1.x, fmaf(hv.y, w1.y, fmaf(hv.z, w1.z, hv.w * w1.w)));
    float s2 = fmaf(hv.x, w2.x, fmaf(hv.y, w2.y, fmaf(hv.z, w2.z, hv.w * w2.w)));
#pragma unroll
    for (int off = 16; off; off >>= 1) {
        s1 += __shfl_down_sync(0xffffffffu, s1, off);
        s2 += __shfl_down_sync(0xffffffffu, s2, off);
    }
    if (lane == 0) { g_d1[gw] = s1; g_d2[gw] = s2; }
}

// ---------------------------------------------------------------------------
// A2: place edges into per-row buckets with PRECOMPUTED values (dots done).
//     ILP x4: all independent loads batched, 8 gathers + 4 atomics in flight.
// ---------------------------------------------------------------------------
__global__ void place_kernel(const int*   __restrict__ src,
                             const int*   __restrict__ dst,
                             const float* __restrict__ wts,
                             const float* __restrict__ W,
                             const float* __restrict__ b) {
    int t  = (int)(blockIdx.x * blockDim.x + threadIdx.x);
    int e0 = t * 4;
    if (e0 >= E_EDGES) return;          // E multiple of 4

    int4   s4 = *(const int4*)  (src + e0);
    int4   d4 = *(const int4*)  (dst + e0);
    float4 w4 = *(const float4*)(wts + e0);
    float wlin = __ldg(&W[2 * H_DIM]);
    float bias = __ldg(&b[0]);

    float a0 = g_d1[d4.x], a1 = g_d1[d4.y], a2 = g_d1[d4.z], a3 = g_d1[d4.w];
    float c0 = g_d2[s4.x], c1 = g_d2[s4.y], c2 = g_d2[s4.z], c3 = g_d2[s4.w];

    int p0 = atomicAdd(&g_cursor[d4.x], 1);
    int p1 = atomicAdd(&g_cursor[d4.y], 1);
    int p2 = atomicAdd(&g_cursor[d4.z], 1);
    int p3 = atomicAdd(&g_cursor[d4.w], 1);

    float v0 = a0 + c0 + fmaf(w4.x, wlin, bias);
    float v1 = a1 + c1 + fmaf(w4.y, wlin, bias);
    float v2 = a2 + c2 + fmaf(w4.z, wlin, bias);
    float v3 = a3 + c3 + fmaf(w4.w, wlin, bias);

    if (p0 < CAP) g_bucket[(size_t)d4.x * CAP + p0] = make_int2(s4.x, __float_as_int(v0));
    if (p1 < CAP) g_bucket[(size_t)d4.y * CAP + p1] = make_int2(s4.y, __float_as_int(v1));
    if (p2 < CAP) g_bucket[(size_t)d4.z * CAP + p2] = make_int2(s4.z, __float_as_int(v2));
    if (p3 < CAP) g_bucket[(size_t)d4.w * CAP + p3] = make_int2(s4.w, __float_as_int(v3));
}

// ---------------------------------------------------------------------------
// D: fill + merge (R4-proven structure). Build 48KB row in smem (NEG + this
//    row's precomputed edge values), stream out with __stcs. cnt read hoisted
//    above the fill loop so its latency hides under it. Cursor self-reset.
//    __launch_bounds__(512,4) caps regs so 4 blocks/SM stay resident (1 wave).
// ---------------------------------------------------------------------------
__global__ __launch_bounds__(512, 4) void fill_merge_kernel(float4* __restrict__ out) {
    __shared__ float row[N_NODES];               // exactly 48 KB
    float4* row4 = (float4*)row;
    const float4 v = make_float4(NEGVAL, NEGVAL, NEGVAL, NEGVAL);
    const int tid = threadIdx.x;

    for (int r = blockIdx.x; r < N_NODES; r += gridDim.x) {
        // read count first (broadcast load; latency hidden under fill loop)
        int c   = g_cursor[r];
        int cnt = (c < CAP) ? c : CAP;

#pragma unroll
        for (int i = tid; i < ROW4; i += 512) row4[i] = v;
        __syncthreads();                         // all reads of cursor[r] done

        if (tid == 0) g_cursor[r] = 0;           // self-restore for next launch

        const int2* bkt = &g_bucket[(size_t)r * CAP];
        for (int i = tid; i < cnt; i += 512) {
            int2 ev = bkt[i];
            row[ev.x] = __int_as_float(ev.y);    // dup races benign
        }
        __syncthreads();

        float4* dstp = out + (size_t)r * ROW4;
#pragma unroll
        for (int i = tid; i < ROW4; i += 512) __stcs(&dstp[i], row4[i]);
        __syncthreads();                         // stores done before smem reuse
    }
}

// ---------------------------------------------------------------------------
// Launch. Input order (metadata): h, sources, dests, weights, W, b
// ---------------------------------------------------------------------------
extern "C" void kernel_launch(void* const* d_in, const int* in_sizes, int n_in,
                              void* d_out, int out_size) {
    const float* h       = (const float*)d_in[0];
    const int*   sources = (const int*)  d_in[1];
    const int*   dests   = (const int*)  d_in[2];
    const float* weights = (const float*)d_in[3];
    const float* W       = (const float*)d_in[4];
    const float* b       = (const float*)d_in[5];
    float*       out     = (float*)d_out;

    // A1: dots. N warps.
    dots_kernel<<<(N_NODES * 32) / 256, 256>>>(h, W);

    // A2: place with precomputed values, 4 edges/thread.
    place_kernel<<<(E_EDGES / 4) / 256, 256>>>(sources, dests, weights, W, b);

    // D: fill + merge. 4 blocks/SM, one wave.
    fill_merge_kernel<<<148 * 4, 512>>>((float4*)out);
}

// round 9
// speedup vs baseline: 1.3923x; 1.0381x over previous
#include <cuda_runtime.h>
#include <cstdint>

#define N_NODES 12288
#define H_DIM   128
#define E_EDGES 393216
#define NEGVAL  (-1000000000.0f)
#define ROW4    (N_NODES / 4)      // 3072 float4 per row
#define CAP     256                // bucket capacity per row (Poisson(32), max~65)

// Static scratch. g_cursor zero-init at load; self-restored by D each launch.
__device__ float g_d1[N_NODES];
__device__ float g_d2[N_NODES];
__device__ int   g_cursor[N_NODES];
__device__ int2  g_bucket[(size_t)N_NODES * CAP];   // (src_col, float_bits(value))

// ---------------------------------------------------------------------------
// A1: per-node dots, 8 nodes per warp (MLP=8 on the h loads).
//     Each of the 8 row-loads is a full-warp coalesced 512B load.
// ---------------------------------------------------------------------------
__global__ void dots_kernel(const float* __restrict__ h,
                            const float* __restrict__ W) {
    int t    = (int)(blockIdx.x * blockDim.x + threadIdx.x);
    int wrp  = t >> 5;
    int lane = t & 31;
    int base = wrp * 8;                 // first node of this warp's group
    if (base >= N_NODES) return;

    const float4* w14 = (const float4*)(W);
    const float4* w24 = (const float4*)(W + H_DIM);
    float4 w1 = __ldg(&w14[lane]);
    float4 w2 = __ldg(&w24[lane]);

    float4 hv[8];
#pragma unroll
    for (int j = 0; j < 8; j++) {       // 8 independent loads in flight
        const float4* hr4 = (const float4*)(h + (size_t)(base + j) * H_DIM);
        hv[j] = __ldg(&hr4[lane]);
    }

    float s1[8], s2[8];
#pragma unroll
    for (int j = 0; j < 8; j++) {
        s1[j] = fmaf(hv[j].x, w1.x, fmaf(hv[j].y, w1.y, fmaf(hv[j].z, w1.z, hv[j].w * w1.w)));
        s2[j] = fmaf(hv[j].x, w2.x, fmaf(hv[j].y, w2.y, fmaf(hv[j].z, w2.z, hv[j].w * w2.w)));
    }
#pragma unroll
    for (int off = 16; off; off >>= 1) {
#pragma unroll
        for (int j = 0; j < 8; j++) {
            s1[j] += __shfl_down_sync(0xffffffffu, s1[j], off);
            s2[j] += __shfl_down_sync(0xffffffffu, s2[j], off);
        }
    }
    if (lane == 0) {
#pragma unroll
        for (int j = 0; j < 8; j++) {
            g_d1[base + j] = s1[j];
            g_d2[base + j] = s2[j];
        }
    }
}

// ---------------------------------------------------------------------------
// A2: place edges into per-row buckets with PRECOMPUTED values. ILP x4.
//     PDL: everything before cudaGridDependencySynchronize() is independent
//     of A1 (edge arrays + cursor atomics); the d1/d2 gathers come after.
// ---------------------------------------------------------------------------
__global__ void place_kernel(const int*   __restrict__ src,
                             const int*   __restrict__ dst,
                             const float* __restrict__ wts,
                             const float* __restrict__ W,
                             const float* __restrict__ b) {
    int t  = (int)(blockIdx.x * blockDim.x + threadIdx.x);
    int e0 = t * 4;
    if (e0 >= E_EDGES) return;          // E multiple of 4

    int4   s4 = *(const int4*)  (src + e0);
    int4   d4 = *(const int4*)  (dst + e0);
    float4 w4 = *(const float4*)(wts + e0);
    float wlin = __ldg(&W[2 * H_DIM]);
    float bias = __ldg(&b[0]);

    int p0 = atomicAdd(&g_cursor[d4.x], 1);
    int p1 = atomicAdd(&g_cursor[d4.y], 1);
    int p2 = atomicAdd(&g_cursor[d4.z], 1);
    int p3 = atomicAdd(&g_cursor[d4.w], 1);

    cudaGridDependencySynchronize();    // wait for A1's d1/d2

    float a0 = g_d1[d4.x], a1 = g_d1[d4.y], a2 = g_d1[d4.z], a3 = g_d1[d4.w];
    float c0 = g_d2[s4.x], c1 = g_d2[s4.y], c2 = g_d2[s4.z], c3 = g_d2[s4.w];

    float v0 = a0 + c0 + fmaf(w4.x, wlin, bias);
    float v1 = a1 + c1 + fmaf(w4.y, wlin, bias);
    float v2 = a2 + c2 + fmaf(w4.z, wlin, bias);
    float v3 = a3 + c3 + fmaf(w4.w, wlin, bias);

    if (p0 < CAP) g_bucket[(size_t)d4.x * CAP + p0] = make_int2(s4.x, __float_as_int(v0));
    if (p1 < CAP) g_bucket[(size_t)d4.y * CAP + p1] = make_int2(s4.y, __float_as_int(v1));
    if (p2 < CAP) g_bucket[(size_t)d4.z * CAP + p2] = make_int2(s4.z, __float_as_int(v2));
    if (p3 < CAP) g_bucket[(size_t)d4.w * CAP + p3] = make_int2(s4.w, __float_as_int(v3));
}

// ---------------------------------------------------------------------------
// D: fill + merge (R4-proven structure). PDL: the first row's NEG smem fill
//    runs before cudaGridDependencySynchronize() (touches no global state),
//    overlapping A2's tail. Cursor self-reset keeps replays deterministic.
// ---------------------------------------------------------------------------
__global__ __launch_bounds__(512, 4) void fill_merge_kernel(float4* __restrict__ out) {
    __shared__ float row[N_NODES];               // exactly 48 KB
    float4* row4 = (float4*)row;
    const float4 v = make_float4(NEGVAL, NEGVAL, NEGVAL, NEGVAL);
    const int tid = threadIdx.x;

    // Prefill first row's smem while A2 drains (independent of globals).
#pragma unroll
    for (int i = tid; i < ROW4; i += 512) row4[i] = v;

    cudaGridDependencySynchronize();             // buckets + cursors ready

    bool first = true;
    for (int r = blockIdx.x; r < N_NODES; r += gridDim.x) {
        // broadcast count read; latency hidden under (re)fill
        int c   = g_cursor[r];
        int cnt = (c < CAP) ? c : CAP;

        if (!first) {
#pragma unroll
            for (int i = tid; i < ROW4; i += 512) row4[i] = v;
        }
        first = false;
        __syncthreads();                         // all cursor[r] reads done

        if (tid == 0) g_cursor[r] = 0;           // self-restore for next launch

        const int2* bkt = &g_bucket[(size_t)r * CAP];
        for (int i = tid; i < cnt; i += 512) {
            int2 ev = bkt[i];
            row[ev.x] = __int_as_float(ev.y);    // dup races benign
        }
        __syncthreads();

        float4* dstp = out + (size_t)r * ROW4;
#pragma unroll
        for (int i = tid; i < ROW4; i += 512) __stcs(&dstp[i], row4[i]);
        __syncthreads();                         // stores done before smem reuse
    }
}

// ---------------------------------------------------------------------------
// Launch. Input order (metadata): h, sources, dests, weights, W, b
// A1 is a plain launch (serializes against the previous replay's D).
// A2 and D carry the PDL stream-serialization attribute.
// ---------------------------------------------------------------------------
extern "C" void kernel_launch(void* const* d_in, const int* in_sizes, int n_in,
                              void* d_out, int out_size) {
    const float* h       = (const float*)d_in[0];
    const int*   sources = (const int*)  d_in[1];
    const int*   dests   = (const int*)  d_in[2];
    const float* weights = (const float*)d_in[3];
    const float* W       = (const float*)d_in[4];
    const float* b       = (const float*)d_in[5];
    float*       out     = (float*)d_out;

    // A1: dots, 8 nodes/warp. 1536 warps -> 192 blocks.
    dots_kernel<<<(N_NODES / 8 * 32) / 256, 256>>>(h, W);

    cudaLaunchAttribute pdl[1];
    pdl[0].id = cudaLaunchAttributeProgrammaticStreamSerialization;
    pdl[0].val.programmaticStreamSerializationAllowed = 1;

    // A2: place (PDL over A1). 4 edges/thread -> 384 blocks.
    {
        cudaLaunchConfig_t cfg = {};
        cfg.gridDim  = dim3((E_EDGES / 4) / 256);
        cfg.blockDim = dim3(256);
        cfg.attrs    = pdl;
        cfg.numAttrs = 1;
        cudaLaunchKernelEx(&cfg, place_kernel, sources, dests, weights, W, b);
    }

    // D: fill + merge (PDL over A2). 4 blocks/SM, one wave.
    {
        cudaLaunchConfig_t cfg = {};
        cfg.gridDim  = dim3(148 * 4);
        cfg.blockDim = dim3(512);
        cfg.attrs    = pdl;
        cfg.numAttrs = 1;
        cudaLaunchKernelEx(&cfg, fill_merge_kernel, (float4*)out);
    }
}